// round 14
// baseline (speedup 1.0000x reference)
#include <cuda_runtime.h>
#include <cuda_bf16.h>
#include <cstddef>
#include <cstdint>

#define BB 64
#define SSQ 2048
#define II 256
#define HH 256

// ---------------- scratch (device globals; allocation is forbidden) ----------------
__device__ float g_preA[33554432];   // 2048*64*256
__device__ float g_preB[33554432];   // 2048*64*256
__device__ float g_y0[67108864];     // 2048*64*512

// ---------------- init: zero hn tail of output ----------------
__global__ void init_kernel(float* __restrict__ hn, int n) {
    int i = blockIdx.x * blockDim.x + threadIdx.x;
    if (i < n) hn[i] = 0.0f;
}

// no-op: shifts ncu's captured launch (-s 5 -c 1) onto scan2 instead of gemm
__global__ void dummy_kernel() {}

// ---------------- helpers ----------------
__device__ __forceinline__ uint32_t smem_u32(const void* p) {
    uint32_t a;
    asm("{ .reg .u64 t; cvta.to.shared.u64 t, %1; cvt.u32.u64 %0, t; }"
        : "=r"(a) : "l"(p));
    return a;
}

// fast tanh: 1 - 2/(e^{2x}+1); MUFU-based, rel err ~1e-6
__device__ __forceinline__ float fast_tanh(float x) {
    float e = __expf(2.0f * x);
    return 1.0f - __fdividef(2.0f, e + 1.0f);
}

// packed f32x2 FMA (Blackwell): d = a*b + d elementwise on 2 floats
__device__ __forceinline__ void fma2(unsigned long long& d, unsigned long long a,
                                     unsigned long long b) {
    asm("fma.rn.f32x2 %0, %1, %2, %0;" : "+l"(d) : "l"(a), "l"(b));
}
__device__ __forceinline__ unsigned long long add2(unsigned long long a,
                                                   unsigned long long b) {
    unsigned long long d;
    asm("add.rn.f32x2 %0, %1, %2;" : "=l"(d) : "l"(a), "l"(b));
    return d;
}
__device__ __forceinline__ float hsum2(unsigned long long v) {
    uint32_t lo, hi;
    asm("mov.b64 {%0, %1}, %2;" : "=r"(lo), "=r"(hi) : "l"(v));
    return __uint_as_float(lo) + __uint_as_float(hi);
}

// float4 -> packed bf16 hi pair/lo pair (hi = rn(x), lo = rn(x - hi))
__device__ __forceinline__ void split_f4(float4 f, uint32_t& h01, uint32_t& h23,
                                         uint32_t& l01, uint32_t& l23) {
    asm("cvt.rn.bf16x2.f32 %0, %1, %2;" : "=r"(h01) : "f"(f.y), "f"(f.x));
    asm("cvt.rn.bf16x2.f32 %0, %1, %2;" : "=r"(h23) : "f"(f.w), "f"(f.z));
    float h0 = __uint_as_float(h01 << 16);
    float h1 = __uint_as_float(h01 & 0xffff0000u);
    float h2 = __uint_as_float(h23 << 16);
    float h3 = __uint_as_float(h23 & 0xffff0000u);
    float l0 = f.x - h0, l1 = f.y - h1, l2 = f.z - h2, l3 = f.w - h3;
    asm("cvt.rn.bf16x2.f32 %0, %1, %2;" : "=r"(l01) : "f"(l1), "f"(l0));
    asm("cvt.rn.bf16x2.f32 %0, %1, %2;" : "=r"(l23) : "f"(l3), "f"(l2));
}

__device__ __forceinline__ void sts_v2(uint32_t addr, uint32_t a, uint32_t b) {
    asm volatile("st.shared.v2.b32 [%0], {%1, %2};" :: "r"(addr), "r"(a), "r"(b)
                 : "memory");
}

__device__ __forceinline__ void ldsm_x4(uint32_t addr, uint32_t& r0, uint32_t& r1,
                                        uint32_t& r2, uint32_t& r3) {
    asm volatile("ldmatrix.sync.aligned.m8n8.x4.shared.b16 {%0,%1,%2,%3}, [%4];"
                 : "=r"(r0), "=r"(r1), "=r"(r2), "=r"(r3) : "r"(addr));
}

__device__ __forceinline__ void mma16816(float* c, const uint32_t* a,
                                         const uint32_t* b) {
    asm volatile(
        "mma.sync.aligned.m16n8k16.row.col.f32.bf16.bf16.f32 "
        "{%0,%1,%2,%3}, {%4,%5,%6,%7}, {%8,%9}, {%0,%1,%2,%3};"
        : "+f"(c[0]), "+f"(c[1]), "+f"(c[2]), "+f"(c[3])
        : "r"(a[0]), "r"(a[1]), "r"(a[2]), "r"(a[3]), "r"(b[0]), "r"(b[1]));
}

// ---------------- tensor-core (HMMA mma.sync) input-projection GEMM ----------------
// (unchanged: ping-pong SMEM, bf16 hi/lo split, ~615us for K=512)
template <int K, int MODE>
__global__ __launch_bounds__(256) void gemm_pre_mma(
    const float* __restrict__ A,
    const float* __restrict__ Wf, const float* __restrict__ Wb,
    const float* __restrict__ bf, const float* __restrict__ bb,
    int ldw,
    float* __restrict__ outF, float* __restrict__ outB)
{
    extern __shared__ __align__(16) unsigned char smem[];   // 2 x 40960 B

    const int tid  = threadIdx.x;
    const int wid  = tid >> 5;
    const int lane = tid & 31;
    const int warp_m = wid >> 2;
    const int warp_n = wid & 3;

    const int m0  = blockIdx.y * 128;
    const int nblk = blockIdx.x;
    const float* W    = (nblk < 2) ? Wf : Wb;
    const float* bias = (nblk < 2) ? bf : bb;
    float*       outp = (nblk < 2) ? outF : outB;
    const int n0 = (nblk & 1) * 128;

    const uint32_t sbase = smem_u32(smem);

    const int row  = tid >> 1;
    const int half = tid & 1;

    const float* arow;
    {
        int ma = m0 + row;
        if (MODE == 0)
            arow = A + ((size_t)(ma & 63) * SSQ + (size_t)(ma >> 6)) * II;
        else
            arow = A + (size_t)ma * K;
    }
    const float* wrow = W + (size_t)(n0 + row) * ldw;

    float acc[4][4][4];
#pragma unroll
    for (int mt = 0; mt < 4; mt++)
#pragma unroll
        for (int nt = 0; nt < 4; nt++)
#pragma unroll
            for (int q = 0; q < 4; q++) acc[mt][nt][q] = 0.0f;

    const uint32_t stoff = (uint32_t)(row * 80 + half * 32);

    float4 av[4], wv[4];
#pragma unroll
    for (int j = 0; j < 4; j++) {
        av[j] = *(const float4*)(arow + half * 16 + j * 4);
        wv[j] = *(const float4*)(wrow + half * 16 + j * 4);
    }
#pragma unroll
    for (int j = 0; j < 4; j++) {
        uint32_t h01, h23, l01, l23;
        split_f4(av[j], h01, h23, l01, l23);
        sts_v2(sbase + stoff + j * 8,          h01, h23);
        sts_v2(sbase + 10240u + stoff + j * 8, l01, l23);
        split_f4(wv[j], h01, h23, l01, l23);
        sts_v2(sbase + 20480u + stoff + j * 8, h01, h23);
        sts_v2(sbase + 30720u + stoff + j * 8, l01, l23);
    }
    const int NCH = K / 32;
    if (NCH > 1) {
#pragma unroll
        for (int j = 0; j < 4; j++) {
            av[j] = *(const float4*)(arow + 32 + half * 16 + j * 4);
            wv[j] = *(const float4*)(wrow + 32 + half * 16 + j * 4);
        }
    }
    __syncthreads();

#pragma unroll 1
    for (int ck = 0; ck < NCH; ck++) {
        const uint32_t cur = sbase + (uint32_t)(ck & 1) * 40960u;
        const uint32_t nxt = sbase + (uint32_t)((ck + 1) & 1) * 40960u;

        uint32_t ahi[2][4][4], alo[2][4][4];
        uint32_t bhi[2][4][2], blo[2][4][2];
#pragma unroll
        for (int ks = 0; ks < 2; ks++) {
#pragma unroll
            for (int mt = 0; mt < 4; mt++) {
                uint32_t off = (uint32_t)((warp_m * 64 + mt * 16 + (lane & 15)) * 80
                                          + ks * 32 + ((lane >> 4) << 4));
                ldsm_x4(cur + off, ahi[ks][mt][0], ahi[ks][mt][1],
                        ahi[ks][mt][2], ahi[ks][mt][3]);
                ldsm_x4(cur + 10240u + off, alo[ks][mt][0], alo[ks][mt][1],
                        alo[ks][mt][2], alo[ks][mt][3]);
            }
#pragma unroll
            for (int np = 0; np < 2; np++) {
                int nr = warp_n * 32 + np * 16 + (lane & 7) + ((lane & 16) >> 1);
                uint32_t off = (uint32_t)(nr * 80 + ks * 32 + ((lane >> 3) & 1) * 16);
                uint32_t r0, r1, r2, r3;
                ldsm_x4(cur + 20480u + off, r0, r1, r2, r3);
                bhi[ks][np * 2][0] = r0; bhi[ks][np * 2][1] = r1;
                bhi[ks][np * 2 + 1][0] = r2; bhi[ks][np * 2 + 1][1] = r3;
                ldsm_x4(cur + 30720u + off, r0, r1, r2, r3);
                blo[ks][np * 2][0] = r0; blo[ks][np * 2][1] = r1;
                blo[ks][np * 2 + 1][0] = r2; blo[ks][np * 2 + 1][1] = r3;
            }
        }

        if (ck + 1 < NCH) {
#pragma unroll
            for (int j = 0; j < 4; j++) {
                uint32_t h01, h23, l01, l23;
                split_f4(av[j], h01, h23, l01, l23);
                sts_v2(nxt + stoff + j * 8,          h01, h23);
                sts_v2(nxt + 10240u + stoff + j * 8, l01, l23);
                split_f4(wv[j], h01, h23, l01, l23);
                sts_v2(nxt + 20480u + stoff + j * 8, h01, h23);
                sts_v2(nxt + 30720u + stoff + j * 8, l01, l23);
            }
        }
        if (ck + 2 < NCH) {
            const int kb = (ck + 2) * 32 + half * 16;
#pragma unroll
            for (int j = 0; j < 4; j++) {
                av[j] = *(const float4*)(arow + kb + j * 4);
                wv[j] = *(const float4*)(wrow + kb + j * 4);
            }
        }

#pragma unroll
        for (int ks = 0; ks < 2; ks++) {
#pragma unroll
            for (int mt = 0; mt < 4; mt++)
#pragma unroll
                for (int nt = 0; nt < 4; nt++)
                    mma16816(acc[mt][nt], ahi[ks][mt], bhi[ks][nt]);
#pragma unroll
            for (int mt = 0; mt < 4; mt++)
#pragma unroll
                for (int nt = 0; nt < 4; nt++)
                    mma16816(acc[mt][nt], ahi[ks][mt], blo[ks][nt]);
#pragma unroll
            for (int mt = 0; mt < 4; mt++)
#pragma unroll
                for (int nt = 0; nt < 4; nt++)
                    mma16816(acc[mt][nt], alo[ks][mt], bhi[ks][nt]);
        }
        __syncthreads();
    }

#pragma unroll
    for (int mt = 0; mt < 4; mt++) {
        const int mlo = m0 + warp_m * 64 + mt * 16 + (lane >> 2);
#pragma unroll
        for (int nt = 0; nt < 4; nt++) {
            const int n = n0 + warp_n * 32 + nt * 8 + (lane & 3) * 2;
            float2 bv = *(const float2*)(bias + n);
            float2 v0, v1;
            v0.x = acc[mt][nt][0] + bv.x;
            v0.y = acc[mt][nt][1] + bv.y;
            v1.x = acc[mt][nt][2] + bv.x;
            v1.y = acc[mt][nt][3] + bv.y;
            *(float2*)(outp + (size_t)mlo * 256 + n)       = v0;
            *(float2*)(outp + (size_t)(mlo + 8) * 256 + n) = v1;
        }
    }
}

// ---------------- batch-parallel recurrent scan (cluster of 2, mbarrier sync) ----
// Same as R12 (best) plus DOUBLE pre-prefetch: pre(t+2) is fetched at step t,
// giving each DRAM load >= 2 full steps of slack.
__global__ __launch_bounds__(512, 1) __cluster_dims__(2, 1, 1)
void scan2(const float* __restrict__ preF, const float* __restrict__ preB,
           const float* __restrict__ W_f, const float* __restrict__ W_b,
           int ldw, int whofs,
           float* __restrict__ out, size_t sS, size_t sB)
{
    __shared__ float hb[2 * 2 * 272];   // [parity][rec][272]
    __shared__ __align__(8) uint64_t s_mbar[2];

    const int tid = threadIdx.x;
    const int kq  = tid & 3;
    const int o   = tid >> 2;          // 0..127
    uint32_t r;
    asm("mov.u32 %0, %%cluster_ctarank;" : "=r"(r));
    const int cl    = blockIdx.x >> 1;
    const int dir   = cl >> 5;
    const int bpair = (cl & 31) * 2;
    const int colg  = (int)r * 128 + o;

    const float* pre = dir ? preB : preF;
    const float* W   = dir ? W_b : W_f;

    // load my 64 weights into registers as 32 packed f32x2
    unsigned long long w2[32];
    {
        const float* wp = W + (size_t)colg * ldw + whofs + kq * 64;
#pragma unroll
        for (int i = 0; i < 16; i++) {
            ulonglong2 v = *(const ulonglong2*)(wp + i * 4);
            w2[2 * i]     = v.x;
            w2[2 * i + 1] = v.y;
        }
    }

    const bool active = (kq < 2);          // lanes that own a (rec, col) output
    const int  myb    = bpair + kq;        // batch for my rec (valid if active)

    const uint32_t hb_base = smem_u32(hb);
    const uint32_t mb_local = smem_u32(s_mbar);
    uint32_t mb_peer;
    asm("mapa.shared::cluster.u32 %0, %1, %2;"
        : "=r"(mb_peer) : "r"(mb_local), "r"(r ^ 1u));

    if (tid == 0) {
        asm volatile("mbarrier.init.shared.b64 [%0], 1;" :: "r"(mb_local) : "memory");
        asm volatile("mbarrier.init.shared.b64 [%0], 1;" :: "r"(mb_local + 8u) : "memory");
    }
    // one-time: both CTAs' mbarrier inits visible before any remote arrive
    asm volatile("barrier.cluster.arrive.aligned;" ::: "memory");
    asm volatile("barrier.cluster.wait.aligned;" ::: "memory");

    // precompute peer address for my h slot (parity 0)
    const int hidx0 = kq * 272 + (colg >> 6) * 68 + (colg & 63);
    uint32_t raddr0 = 0;
    if (active) {
        uint32_t laddr = hb_base + (uint32_t)hidx0 * 4u;
        asm("mapa.shared::cluster.u32 %0, %1, %2;"
            : "=r"(raddr0) : "r"(laddr), "r"(r ^ 1u));
    }

    int s = dir ? 2047 : 0;
    const int sstep = dir ? -1 : 1;

    // double prefetch: pval = pre(t), pvaln = pre(t+1)
    float pval = 0.f, pvaln = 0.f;
    if (active) {
        pval  = __ldg(pre + ((size_t)s * 64 + myb) * 256 + colg);
        pvaln = __ldg(pre + ((size_t)(s + sstep) * 64 + myb) * 256 + colg);
    }

    float* outp = out + (size_t)myb * sB + (size_t)dir * 256 + colg;

    int par = 0;
    for (int t = 0; t < 2048; ++t) {
        float sum0 = 0.f, sum1 = 0.f;
        if (t > 0) {
            unsigned long long p00 = 0ull, p01 = 0ull, p10 = 0ull, p11 = 0ull;
            const float* h0 = &hb[par * 544 + 0 * 272 + kq * 68];
            const float* h1 = &hb[par * 544 + 1 * 272 + kq * 68];
#pragma unroll
            for (int i = 0; i < 16; i++) {
                ulonglong2 h = *(const ulonglong2*)(h0 + i * 4);
                fma2(p00, w2[2 * i],     h.x);
                fma2(p01, w2[2 * i + 1], h.y);
            }
#pragma unroll
            for (int i = 0; i < 16; i++) {
                ulonglong2 h = *(const ulonglong2*)(h1 + i * 4);
                fma2(p10, w2[2 * i],     h.x);
                fma2(p11, w2[2 * i + 1], h.y);
            }
            sum0 = hsum2(add2(p00, p01));
            sum1 = hsum2(add2(p10, p11));
            // reduce over the 4 kq lanes (lane bits 0,1)
            sum0 += __shfl_xor_sync(0xffffffffu, sum0, 1);
            sum0 += __shfl_xor_sync(0xffffffffu, sum0, 2);
            sum1 += __shfl_xor_sync(0xffffffffu, sum1, 1);
            sum1 += __shfl_xor_sync(0xffffffffu, sum1, 2);
        }

        float hnew = 0.f;
        if (active) {
            float acc = (kq == 0) ? sum0 : sum1;
            hnew = fast_tanh(pval + acc);
        }

        if (t < 2047) {
            const int np = par ^ 1;
            if (active) {
                const int hidx = np * 544 + hidx0;
                hb[hidx] = hnew;                        // own buffer
                uint32_t raddr = raddr0 + (uint32_t)(np * 544) * 4u;
                asm volatile("st.shared::cluster.f32 [%0], %1;"
                             :: "r"(raddr), "f"(hnew) : "memory");
            }
            // CTA-wide happens-before for all h stores, then ONE remote
            // release-arrive publishes them to the peer.
            __syncthreads();
            if (tid == 0) {
                asm volatile(
                    "mbarrier.arrive.release.cluster.shared::cluster.b64 _, [%0];"
                    :: "r"(mb_peer + (uint32_t)((t & 1) * 8)) : "memory");
            }

            // overlap with arrive flight: out store + prefetch pre(t+2)
            if (active) __stcg(outp + (size_t)s * sS, hnew);
            s += sstep;
            float pnew = 0.f;
            if (active && (t + 2) < 2048)
                pnew = __ldg(pre + ((size_t)(s + sstep) * 64 + myb) * 256 + colg);
            pval = pvaln;
            pvaln = pnew;

            // wait for the peer's single arrive on mbar[t&1], phase (t>>1)&1
            {
                const uint32_t mb = mb_local + (uint32_t)((t & 1) * 8);
                const uint32_t ph = (uint32_t)((t >> 1) & 1);
                uint32_t done;
                do {
                    asm volatile(
                        "{\n\t.reg .pred p;\n\t"
                        "mbarrier.try_wait.parity.acquire.cluster.shared::cta.b64 "
                        "p, [%1], %2, 0x989680;\n\t"
                        "selp.b32 %0, 1, 0, p;\n\t}"
                        : "=r"(done) : "r"(mb), "r"(ph) : "memory");
                } while (!done);
            }
            par = np;
        } else {
            if (active) __stcg(outp + (size_t)s * sS, hnew);
        }
    }
}

// ---------------- launch ----------------
extern "C" void kernel_launch(void* const* d_in, const int* in_sizes, int n_in,
                              void* d_out, int out_size) {
    const float* x   = (const float*)d_in[0];
    const float* W0f = (const float*)d_in[1];
    const float* b0f = (const float*)d_in[2];
    const float* W0b = (const float*)d_in[3];
    const float* b0b = (const float*)d_in[4];
    const float* W1f = (const float*)d_in[5];
    const float* b1f = (const float*)d_in[6];
    const float* W1b = (const float*)d_in[7];
    const float* b1b = (const float*)d_in[8];
    float* out = (float*)d_out;

    float *preF, *preB, *y0;
    cudaGetSymbolAddress((void**)&preF, g_preA);
    cudaGetSymbolAddress((void**)&preB, g_preB);
    cudaGetSymbolAddress((void**)&y0,   g_y0);

    const size_t OUT_ELEMS = (size_t)BB * SSQ * 2 * HH;   // 67108864
    const int HN_ELEMS = 4 * BB * HH;                     // 65536
    const int SMEM_DYN = 2 * 40960;                       // 80 KB ping-pong

    cudaFuncSetAttribute(gemm_pre_mma<256, 0>,
                         cudaFuncAttributeMaxDynamicSharedMemorySize, SMEM_DYN);
    cudaFuncSetAttribute(gemm_pre_mma<512, 1>,
                         cudaFuncAttributeMaxDynamicSharedMemorySize, SMEM_DYN);

    // zero hn
    init_kernel<<<256, 256>>>(out + OUT_ELEMS, HN_ELEMS);

    // no-op launch: shifts the ncu-captured node onto scan2 (diagnostics)
    dummy_kernel<<<1, 32>>>();

    // layer 0: pre = x @ Wx^T + b  (K=256, Wx = W0*[:, 0:256], ldw=512)
    gemm_pre_mma<256, 0><<<dim3(4, 1024), 256, SMEM_DYN>>>(
        x, W0f, W0b, b0f, b0b, 512, preF, preB);

    // layer 0 scan -> y0 [s][b][512] (fwd cols 0:256, bwd 256:512)
    scan2<<<128, 512>>>(preF, preB, W0f, W0b, 512, 256,
                        y0, (size_t)BB * 512, (size_t)512);

    // layer 1: pre = y0 @ Wx^T + b  (K=512, Wx = W1*[:, 0:512], ldw=768)
    gemm_pre_mma<512, 1><<<dim3(4, 1024), 256, SMEM_DYN>>>(
        y0, W1f, W1b, b1f, b1b, 768, preF, preB);

    // layer 1 scan -> out[b][s][512]
    scan2<<<128, 512>>>(preF, preB, W1f, W1b, 768, 512,
                        out, (size_t)512, (size_t)SSQ * 512);
}

// round 15
// speedup vs baseline: 1.1758x; 1.1758x over previous
#include <cuda_runtime.h>
#include <cuda_bf16.h>
#include <cstddef>
#include <cstdint>

#define BB 64
#define SSQ 2048
#define II 256
#define HH 256

// ---------------- scratch (device globals; allocation is forbidden) ----------------
__device__ float g_preA[33554432];   // 2048*64*256
__device__ float g_preB[33554432];   // 2048*64*256
__device__ float g_y0[67108864];     // 2048*64*512

// ---------------- init: zero hn tail of output ----------------
__global__ void init_kernel(float* __restrict__ hn, int n) {
    int i = blockIdx.x * blockDim.x + threadIdx.x;
    if (i < n) hn[i] = 0.0f;
}

// no-op: shifts ncu's captured launch (-s 5 -c 1) onto scan2 instead of gemm
__global__ void dummy_kernel() {}

// ---------------- helpers ----------------
__device__ __forceinline__ uint32_t smem_u32(const void* p) {
    uint32_t a;
    asm("{ .reg .u64 t; cvta.to.shared.u64 t, %1; cvt.u32.u64 %0, t; }"
        : "=r"(a) : "l"(p));
    return a;
}

// fast tanh: 1 - 2/(e^{2x}+1); MUFU-based, rel err ~1e-6
__device__ __forceinline__ float fast_tanh(float x) {
    float e = __expf(2.0f * x);
    return 1.0f - __fdividef(2.0f, e + 1.0f);
}

// packed f32x2 FMA (Blackwell): d = a*b + d elementwise on 2 floats
__device__ __forceinline__ void fma2(unsigned long long& d, unsigned long long a,
                                     unsigned long long b) {
    asm("fma.rn.f32x2 %0, %1, %2, %0;" : "+l"(d) : "l"(a), "l"(b));
}
__device__ __forceinline__ unsigned long long add2(unsigned long long a,
                                                   unsigned long long b) {
    unsigned long long d;
    asm("add.rn.f32x2 %0, %1, %2;" : "=l"(d) : "l"(a), "l"(b));
    return d;
}
__device__ __forceinline__ float hsum2(unsigned long long v) {
    uint32_t lo, hi;
    asm("mov.b64 {%0, %1}, %2;" : "=r"(lo), "=r"(hi) : "l"(v));
    return __uint_as_float(lo) + __uint_as_float(hi);
}

// float4 -> packed bf16 hi pair/lo pair (hi = rn(x), lo = rn(x - hi))
__device__ __forceinline__ void split_f4(float4 f, uint32_t& h01, uint32_t& h23,
                                         uint32_t& l01, uint32_t& l23) {
    asm("cvt.rn.bf16x2.f32 %0, %1, %2;" : "=r"(h01) : "f"(f.y), "f"(f.x));
    asm("cvt.rn.bf16x2.f32 %0, %1, %2;" : "=r"(h23) : "f"(f.w), "f"(f.z));
    float h0 = __uint_as_float(h01 << 16);
    float h1 = __uint_as_float(h01 & 0xffff0000u);
    float h2 = __uint_as_float(h23 << 16);
    float h3 = __uint_as_float(h23 & 0xffff0000u);
    float l0 = f.x - h0, l1 = f.y - h1, l2 = f.z - h2, l3 = f.w - h3;
    asm("cvt.rn.bf16x2.f32 %0, %1, %2;" : "=r"(l01) : "f"(l1), "f"(l0));
    asm("cvt.rn.bf16x2.f32 %0, %1, %2;" : "=r"(l23) : "f"(l3), "f"(l2));
}

__device__ __forceinline__ void sts_v2(uint32_t addr, uint32_t a, uint32_t b) {
    asm volatile("st.shared.v2.b32 [%0], {%1, %2};" :: "r"(addr), "r"(a), "r"(b)
                 : "memory");
}

__device__ __forceinline__ void ldsm_x4(uint32_t addr, uint32_t& r0, uint32_t& r1,
                                        uint32_t& r2, uint32_t& r3) {
    asm volatile("ldmatrix.sync.aligned.m8n8.x4.shared.b16 {%0,%1,%2,%3}, [%4];"
                 : "=r"(r0), "=r"(r1), "=r"(r2), "=r"(r3) : "r"(addr));
}

__device__ __forceinline__ void mma16816(float* c, const uint32_t* a,
                                         const uint32_t* b) {
    asm volatile(
        "mma.sync.aligned.m16n8k16.row.col.f32.bf16.bf16.f32 "
        "{%0,%1,%2,%3}, {%4,%5,%6,%7}, {%8,%9}, {%0,%1,%2,%3};"
        : "+f"(c[0]), "+f"(c[1]), "+f"(c[2]), "+f"(c[3])
        : "r"(a[0]), "r"(a[1]), "r"(a[2]), "r"(a[3]), "r"(b[0]), "r"(b[1]));
}

// ---------------- tensor-core (HMMA mma.sync) input-projection GEMM ----------------
// (unchanged: ping-pong SMEM, bf16 hi/lo split, ~615us for K=512)
template <int K, int MODE>
__global__ __launch_bounds__(256) void gemm_pre_mma(
    const float* __restrict__ A,
    const float* __restrict__ Wf, const float* __restrict__ Wb,
    const float* __restrict__ bf, const float* __restrict__ bb,
    int ldw,
    float* __restrict__ outF, float* __restrict__ outB)
{
    extern __shared__ __align__(16) unsigned char smem[];   // 2 x 40960 B

    const int tid  = threadIdx.x;
    const int wid  = tid >> 5;
    const int lane = tid & 31;
    const int warp_m = wid >> 2;
    const int warp_n = wid & 3;

    const int m0  = blockIdx.y * 128;
    const int nblk = blockIdx.x;
    const float* W    = (nblk < 2) ? Wf : Wb;
    const float* bias = (nblk < 2) ? bf : bb;
    float*       outp = (nblk < 2) ? outF : outB;
    const int n0 = (nblk & 1) * 128;

    const uint32_t sbase = smem_u32(smem);

    const int row  = tid >> 1;
    const int half = tid & 1;

    const float* arow;
    {
        int ma = m0 + row;
        if (MODE == 0)
            arow = A + ((size_t)(ma & 63) * SSQ + (size_t)(ma >> 6)) * II;
        else
            arow = A + (size_t)ma * K;
    }
    const float* wrow = W + (size_t)(n0 + row) * ldw;

    float acc[4][4][4];
#pragma unroll
    for (int mt = 0; mt < 4; mt++)
#pragma unroll
        for (int nt = 0; nt < 4; nt++)
#pragma unroll
            for (int q = 0; q < 4; q++) acc[mt][nt][q] = 0.0f;

    const uint32_t stoff = (uint32_t)(row * 80 + half * 32);

    float4 av[4], wv[4];
#pragma unroll
    for (int j = 0; j < 4; j++) {
        av[j] = *(const float4*)(arow + half * 16 + j * 4);
        wv[j] = *(const float4*)(wrow + half * 16 + j * 4);
    }
#pragma unroll
    for (int j = 0; j < 4; j++) {
        uint32_t h01, h23, l01, l23;
        split_f4(av[j], h01, h23, l01, l23);
        sts_v2(sbase + stoff + j * 8,          h01, h23);
        sts_v2(sbase + 10240u + stoff + j * 8, l01, l23);
        split_f4(wv[j], h01, h23, l01, l23);
        sts_v2(sbase + 20480u + stoff + j * 8, h01, h23);
        sts_v2(sbase + 30720u + stoff + j * 8, l01, l23);
    }
    const int NCH = K / 32;
    if (NCH > 1) {
#pragma unroll
        for (int j = 0; j < 4; j++) {
            av[j] = *(const float4*)(arow + 32 + half * 16 + j * 4);
            wv[j] = *(const float4*)(wrow + 32 + half * 16 + j * 4);
        }
    }
    __syncthreads();

#pragma unroll 1
    for (int ck = 0; ck < NCH; ck++) {
        const uint32_t cur = sbase + (uint32_t)(ck & 1) * 40960u;
        const uint32_t nxt = sbase + (uint32_t)((ck + 1) & 1) * 40960u;

        uint32_t ahi[2][4][4], alo[2][4][4];
        uint32_t bhi[2][4][2], blo[2][4][2];
#pragma unroll
        for (int ks = 0; ks < 2; ks++) {
#pragma unroll
            for (int mt = 0; mt < 4; mt++) {
                uint32_t off = (uint32_t)((warp_m * 64 + mt * 16 + (lane & 15)) * 80
                                          + ks * 32 + ((lane >> 4) << 4));
                ldsm_x4(cur + off, ahi[ks][mt][0], ahi[ks][mt][1],
                        ahi[ks][mt][2], ahi[ks][mt][3]);
                ldsm_x4(cur + 10240u + off, alo[ks][mt][0], alo[ks][mt][1],
                        alo[ks][mt][2], alo[ks][mt][3]);
            }
#pragma unroll
            for (int np = 0; np < 2; np++) {
                int nr = warp_n * 32 + np * 16 + (lane & 7) + ((lane & 16) >> 1);
                uint32_t off = (uint32_t)(nr * 80 + ks * 32 + ((lane >> 3) & 1) * 16);
                uint32_t r0, r1, r2, r3;
                ldsm_x4(cur + 20480u + off, r0, r1, r2, r3);
                bhi[ks][np * 2][0] = r0; bhi[ks][np * 2][1] = r1;
                bhi[ks][np * 2 + 1][0] = r2; bhi[ks][np * 2 + 1][1] = r3;
                ldsm_x4(cur + 30720u + off, r0, r1, r2, r3);
                blo[ks][np * 2][0] = r0; blo[ks][np * 2][1] = r1;
                blo[ks][np * 2 + 1][0] = r2; blo[ks][np * 2 + 1][1] = r3;
            }
        }

        if (ck + 1 < NCH) {
#pragma unroll
            for (int j = 0; j < 4; j++) {
                uint32_t h01, h23, l01, l23;
                split_f4(av[j], h01, h23, l01, l23);
                sts_v2(nxt + stoff + j * 8,          h01, h23);
                sts_v2(nxt + 10240u + stoff + j * 8, l01, l23);
                split_f4(wv[j], h01, h23, l01, l23);
                sts_v2(nxt + 20480u + stoff + j * 8, h01, h23);
                sts_v2(nxt + 30720u + stoff + j * 8, l01, l23);
            }
        }
        if (ck + 2 < NCH) {
            const int kb = (ck + 2) * 32 + half * 16;
#pragma unroll
            for (int j = 0; j < 4; j++) {
                av[j] = *(const float4*)(arow + kb + j * 4);
                wv[j] = *(const float4*)(wrow + kb + j * 4);
            }
        }

#pragma unroll
        for (int ks = 0; ks < 2; ks++) {
#pragma unroll
            for (int mt = 0; mt < 4; mt++)
#pragma unroll
                for (int nt = 0; nt < 4; nt++)
                    mma16816(acc[mt][nt], ahi[ks][mt], bhi[ks][nt]);
#pragma unroll
            for (int mt = 0; mt < 4; mt++)
#pragma unroll
                for (int nt = 0; nt < 4; nt++)
                    mma16816(acc[mt][nt], ahi[ks][mt], blo[ks][nt]);
#pragma unroll
            for (int mt = 0; mt < 4; mt++)
#pragma unroll
                for (int nt = 0; nt < 4; nt++)
                    mma16816(acc[mt][nt], alo[ks][mt], bhi[ks][nt]);
        }
        __syncthreads();
    }

#pragma unroll
    for (int mt = 0; mt < 4; mt++) {
        const int mlo = m0 + warp_m * 64 + mt * 16 + (lane >> 2);
#pragma unroll
        for (int nt = 0; nt < 4; nt++) {
            const int n = n0 + warp_n * 32 + nt * 8 + (lane & 3) * 2;
            float2 bv = *(const float2*)(bias + n);
            float2 v0, v1;
            v0.x = acc[mt][nt][0] + bv.x;
            v0.y = acc[mt][nt][1] + bv.y;
            v1.x = acc[mt][nt][2] + bv.x;
            v1.y = acc[mt][nt][3] + bv.y;
            *(float2*)(outp + (size_t)mlo * 256 + n)       = v0;
            *(float2*)(outp + (size_t)(mlo + 8) * 256 + n) = v1;
        }
    }
}

// ---------------- batch-parallel scan: split-dot over the exchange ----------------
// 128 CTAs x 512 threads, clusters of 2 (R12 mbarrier protocol). Thread (o,kq):
// col colg = r*128+o, k-chunk split into OWN 32 (k = r*128+kq*32) and PEER 32
// (k = (1-r)*128+kq*32). Own-half partial for step t+1 is computed RIGHT AFTER
// publishing h(t) (local data only) — inside the exchange-latency shadow. After
// the wait only the peer-half partial + shfl/tanh/stores are exposed.
// h SMEM: 32-float blocks @ stride 36, rec stride 300, parity stride 600
// (conflict-free for both chunk reads and 2-rec writes).
__global__ __launch_bounds__(512, 1) __cluster_dims__(2, 1, 1)
void scan2(const float* __restrict__ preF, const float* __restrict__ preB,
           const float* __restrict__ W_f, const float* __restrict__ W_b,
           int ldw, int whofs,
           float* __restrict__ out, size_t sS, size_t sB)
{
    __shared__ float hb[2 * 600];      // [parity][rec][300]
    __shared__ __align__(8) uint64_t s_mbar[2];

    const int tid = threadIdx.x;
    const int kq  = tid & 3;
    const int o   = tid >> 2;          // 0..127
    uint32_t r;
    asm("mov.u32 %0, %%cluster_ctarank;" : "=r"(r));
    const int cl    = blockIdx.x >> 1;
    const int dir   = cl >> 5;
    const int bpair = (cl & 31) * 2;
    const int colg  = (int)r * 128 + o;

    const float* pre = dir ? preB : preF;
    const float* W   = dir ? W_b : W_f;

    // weights: own-half chunk and peer-half chunk, 16 f32x2 each
    unsigned long long wo[16], wp[16];
    {
        const float* base = W + (size_t)colg * ldw + whofs;
        const float* po = base + (int)r * 128 + kq * 32;
        const float* pp = base + (1 - (int)r) * 128 + kq * 32;
#pragma unroll
        for (int i = 0; i < 8; i++) {
            ulonglong2 v = *(const ulonglong2*)(po + i * 4);
            wo[2 * i] = v.x; wo[2 * i + 1] = v.y;
            ulonglong2 u = *(const ulonglong2*)(pp + i * 4);
            wp[2 * i] = u.x; wp[2 * i + 1] = u.y;
        }
    }

    const bool active = (kq < 2);
    const int  myb    = bpair + kq;

    const uint32_t hb_base = smem_u32(hb);
    const uint32_t mb_local = smem_u32(s_mbar);
    uint32_t mb_peer;
    asm("mapa.shared::cluster.u32 %0, %1, %2;"
        : "=r"(mb_peer) : "r"(mb_local), "r"(r ^ 1u));

    if (tid == 0) {
        asm volatile("mbarrier.init.shared.b64 [%0], 1;" :: "r"(mb_local) : "memory");
        asm volatile("mbarrier.init.shared.b64 [%0], 1;" :: "r"(mb_local + 8u) : "memory");
    }
    asm volatile("barrier.cluster.arrive.aligned;" ::: "memory");
    asm volatile("barrier.cluster.wait.aligned;" ::: "memory");

    // write slot: k = colg, rec = kq (active lanes only)
    const int widx  = ((colg >> 5) * 36) + (colg & 31);
    const int hidx0 = kq * 300 + widx;            // parity-0 index
    uint32_t raddr0 = 0;
    if (active) {
        uint32_t laddr = hb_base + (uint32_t)hidx0 * 4u;
        asm("mapa.shared::cluster.u32 %0, %1, %2;"
            : "=r"(raddr0) : "r"(laddr), "r"(r ^ 1u));
    }

    // read chunk float-offsets
    const int roff_own  = ((int)r * 4 + kq) * 36;
    const int roff_peer = ((1 - (int)r) * 4 + kq) * 36;

    int s = dir ? 2047 : 0;
    const int sstep = dir ? -1 : 1;

    float pval = 0.f;
    if (active) pval = __ldg(pre + ((size_t)s * 64 + myb) * 256 + colg);
    float* outp = out + (size_t)myb * sB + (size_t)dir * 256 + colg;

    unsigned long long own0 = 0ull, own1 = 0ull;   // W_own · h_own partials

    for (int t = 0; t < 2048; ++t) {
        float sum0 = 0.f, sum1 = 0.f;
        if (t > 0) {
            const int pp_ = (t - 1) & 1;
            unsigned long long a0 = 0ull, b0 = 0ull, a1 = 0ull, b1 = 0ull;
            const float* h0 = &hb[pp_ * 600 + 0 * 300 + roff_peer];
            const float* h1 = &hb[pp_ * 600 + 1 * 300 + roff_peer];
#pragma unroll
            for (int i = 0; i < 8; i++) {
                ulonglong2 h = *(const ulonglong2*)(h0 + i * 4);
                fma2(a0, wp[2 * i],     h.x);
                fma2(b0, wp[2 * i + 1], h.y);
            }
#pragma unroll
            for (int i = 0; i < 8; i++) {
                ulonglong2 h = *(const ulonglong2*)(h1 + i * 4);
                fma2(a1, wp[2 * i],     h.x);
                fma2(b1, wp[2 * i + 1], h.y);
            }
            sum0 = hsum2(add2(add2(a0, b0), own0));
            sum1 = hsum2(add2(add2(a1, b1), own1));
            sum0 += __shfl_xor_sync(0xffffffffu, sum0, 1);
            sum0 += __shfl_xor_sync(0xffffffffu, sum0, 2);
            sum1 += __shfl_xor_sync(0xffffffffu, sum1, 1);
            sum1 += __shfl_xor_sync(0xffffffffu, sum1, 2);
        }

        float hnew = 0.f;
        if (active) {
            float acc = (kq == 0) ? sum0 : sum1;
            hnew = fast_tanh(pval + acc);
        }

        if (t < 2047) {
            const int np = t & 1;
            if (active) {
                const int idx = np * 600 + hidx0;
                hb[idx] = hnew;                          // own buffer
                uint32_t raddr = raddr0 + (uint32_t)(np * 600) * 4u;
                asm volatile("st.shared::cluster.f32 [%0], %1;"
                             :: "r"(raddr), "f"(hnew) : "memory");
            }
            __syncthreads();                             // own-half visible CTA-wide
            if (tid == 0) {
                asm volatile(
                    "mbarrier.arrive.release.cluster.shared::cluster.b64 _, [%0];"
                    :: "r"(mb_peer + (uint32_t)((t & 1) * 8)) : "memory");
            }

            // ------ exchange-latency shadow: out store, prefetch, OWN-half dot ------
            if (active) __stcg(outp + (size_t)s * sS, hnew);
            s += sstep;
            if (active) pval = __ldg(pre + ((size_t)s * 64 + myb) * 256 + colg);

            {
                unsigned long long a0 = 0ull, b0 = 0ull, a1 = 0ull, b1 = 0ull;
                const float* h0 = &hb[np * 600 + 0 * 300 + roff_own];
                const float* h1 = &hb[np * 600 + 1 * 300 + roff_own];
#pragma unroll
                for (int i = 0; i < 8; i++) {
                    ulonglong2 h = *(const ulonglong2*)(h0 + i * 4);
                    fma2(a0, wo[2 * i],     h.x);
                    fma2(b0, wo[2 * i + 1], h.y);
                }
#pragma unroll
                for (int i = 0; i < 8; i++) {
                    ulonglong2 h = *(const ulonglong2*)(h1 + i * 4);
                    fma2(a1, wo[2 * i],     h.x);
                    fma2(b1, wo[2 * i + 1], h.y);
                }
                own0 = add2(a0, b0);
                own1 = add2(a1, b1);
            }

            // ------ wait for peer's h(t) half ------
            {
                const uint32_t mb = mb_local + (uint32_t)((t & 1) * 8);
                const uint32_t ph = (uint32_t)((t >> 1) & 1);
                uint32_t done;
                do {
                    asm volatile(
                        "{\n\t.reg .pred p;\n\t"
                        "mbarrier.try_wait.parity.acquire.cluster.shared::cta.b64 "
                        "p, [%1], %2, 0x989680;\n\t"
                        "selp.b32 %0, 1, 0, p;\n\t}"
                        : "=r"(done) : "r"(mb), "r"(ph) : "memory");
                } while (!done);
            }
        } else {
            if (active) __stcg(outp + (size_t)s * sS, hnew);
        }
    }
}

// ---------------- launch ----------------
extern "C" void kernel_launch(void* const* d_in, const int* in_sizes, int n_in,
                              void* d_out, int out_size) {
    const float* x   = (const float*)d_in[0];
    const float* W0f = (const float*)d_in[1];
    const float* b0f = (const float*)d_in[2];
    const float* W0b = (const float*)d_in[3];
    const float* b0b = (const float*)d_in[4];
    const float* W1f = (const float*)d_in[5];
    const float* b1f = (const float*)d_in[6];
    const float* W1b = (const float*)d_in[7];
    const float* b1b = (const float*)d_in[8];
    float* out = (float*)d_out;

    float *preF, *preB, *y0;
    cudaGetSymbolAddress((void**)&preF, g_preA);
    cudaGetSymbolAddress((void**)&preB, g_preB);
    cudaGetSymbolAddress((void**)&y0,   g_y0);

    const size_t OUT_ELEMS = (size_t)BB * SSQ * 2 * HH;   // 67108864
    const int HN_ELEMS = 4 * BB * HH;                     // 65536
    const int SMEM_DYN = 2 * 40960;                       // 80 KB ping-pong

    cudaFuncSetAttribute(gemm_pre_mma<256, 0>,
                         cudaFuncAttributeMaxDynamicSharedMemorySize, SMEM_DYN);
    cudaFuncSetAttribute(gemm_pre_mma<512, 1>,
                         cudaFuncAttributeMaxDynamicSharedMemorySize, SMEM_DYN);

    // zero hn
    init_kernel<<<256, 256>>>(out + OUT_ELEMS, HN_ELEMS);

    // no-op launch: keeps the ncu-captured node on scan2 (diagnostics)
    dummy_kernel<<<1, 32>>>();

    // layer 0: pre = x @ Wx^T + b  (K=256, Wx = W0*[:, 0:256], ldw=512)
    gemm_pre_mma<256, 0><<<dim3(4, 1024), 256, SMEM_DYN>>>(
        x, W0f, W0b, b0f, b0b, 512, preF, preB);

    // layer 0 scan -> y0 [s][b][512] (fwd cols 0:256, bwd 256:512)
    scan2<<<128, 512>>>(preF, preB, W0f, W0b, 512, 256,
                        y0, (size_t)BB * 512, (size_t)512);

    // layer 1: pre = y0 @ Wx^T + b  (K=512, Wx = W1*[:, 0:512], ldw=768)
    gemm_pre_mma<512, 1><<<dim3(4, 1024), 256, SMEM_DYN>>>(
        y0, W1f, W1b, b1f, b1b, 768, preF, preB);

    // layer 1 scan -> out[b][s][512]
    scan2<<<128, 512>>>(preF, preB, W1f, W1b, 768, 512,
                        out, (size_t)512, (size_t)SSQ * 512);
}